// round 1
// baseline (speedup 1.0000x reference)
#include <cuda_runtime.h>
#include <math.h>

// Problem constants (fixed shapes from setup_inputs)
#define B_  16
#define L_  4096
#define D_  512
#define C_  512     // 2 * Cin
#define U_  450     // FACTOR * ceil(log(L)) = 50 * 9
#define SCALE_ 0.04419417382415922f   // 1/sqrt(512)

// ---------------- scratch (device globals; no allocation allowed) ----------------
__device__ float g_q[(size_t)B_ * L_ * D_];      // 134 MB  (q in (b,l,d) == Y in (b,o,pos))
__device__ float g_k[(size_t)B_ * L_ * D_];
__device__ float g_v[(size_t)B_ * L_ * D_];
__device__ float g_scores[(size_t)B_ * L_ * U_]; // reused: QKs (b,l,s) then attn (b,u,l)
__device__ float g_ksamp[(size_t)B_ * U_ * D_];
__device__ float g_qsel [(size_t)B_ * U_ * D_];
__device__ float g_upd  [(size_t)B_ * U_ * D_];
__device__ float g_M[B_ * L_];
__device__ int   g_top[B_ * U_];
__device__ float g_part[B_ * 8 * D_];            // partial column sums of V

// =================================================================================
// Projection GEMM: Y = W (512x512) @ X (512x4096) + bias, per (batch, which)
// X rows 0..255 from input_1, 256..511 from input_2. Output row-major (o,pos)
// which IS q/k/v in (l,d) layout (reshape identity).
// Tile 128x128, K-chunk 8, 256 threads, 8x8 per thread. All dims exact multiples.
// =================================================================================
__global__ void proj_kernel(const float* __restrict__ in1, const float* __restrict__ in2,
                            const float* __restrict__ Wq, const float* __restrict__ bq,
                            const float* __restrict__ Wk, const float* __restrict__ bk,
                            const float* __restrict__ Wv, const float* __restrict__ bv)
{
    int z = blockIdx.z;
    int which = z % 3;
    int b     = z / 3;
    const float* W    = (which == 0) ? Wq : (which == 1) ? Wk : Wv;
    const float* bias = (which == 0) ? bq : (which == 1) ? bk : bv;
    float* out = ((which == 0) ? g_q : (which == 1) ? g_k : g_v) + (size_t)b * L_ * D_;
    const float* x1 = in1 + (size_t)b * 256 * 4096;
    const float* x2 = in2 + (size_t)b * 256 * 4096;

    __shared__ __align__(16) float As[8][128];
    __shared__ __align__(16) float Bs[8][128];

    int tid = threadIdx.x;
    int m0 = blockIdx.y * 128, n0 = blockIdx.x * 128;
    int tx = tid & 15, ty = tid >> 4;

    float acc[8][8];
#pragma unroll
    for (int i = 0; i < 8; i++)
#pragma unroll
        for (int j = 0; j < 8; j++) acc[i][j] = 0.f;

    for (int k0 = 0; k0 < 512; k0 += 8) {
        {   // A tile (W): 128 rows x 8 cols
            int r = tid >> 1, cg = (tid & 1) * 4;
            float4 v = *(const float4*)(W + (size_t)(m0 + r) * 512 + k0 + cg);
            As[cg + 0][r] = v.x; As[cg + 1][r] = v.y; As[cg + 2][r] = v.z; As[cg + 3][r] = v.w;
        }
        {   // B tile (X): 8 rows x 128 cols (NN)
            int r = tid >> 5, c = (tid & 31) * 4;
            int gk = k0 + r;
            const float* xr = (gk < 256) ? (x1 + (size_t)gk * 4096)
                                         : (x2 + (size_t)(gk - 256) * 4096);
            float4 v = *(const float4*)(xr + n0 + c);
            Bs[r][c + 0] = v.x; Bs[r][c + 1] = v.y; Bs[r][c + 2] = v.z; Bs[r][c + 3] = v.w;
        }
        __syncthreads();
#pragma unroll
        for (int kk = 0; kk < 8; kk++) {
            float a[8], bb[8];
            *(float4*)(a)     = *(const float4*)&As[kk][ty * 8];
            *(float4*)(a + 4) = *(const float4*)&As[kk][ty * 8 + 4];
            *(float4*)(bb)     = *(const float4*)&Bs[kk][tx * 8];
            *(float4*)(bb + 4) = *(const float4*)&Bs[kk][tx * 8 + 4];
#pragma unroll
            for (int i = 0; i < 8; i++)
#pragma unroll
                for (int j = 0; j < 8; j++) acc[i][j] += a[i] * bb[j];
        }
        __syncthreads();
    }
#pragma unroll
    for (int i = 0; i < 8; i++) {
        int gm = m0 + ty * 8 + i;
        float bv_ = bias[gm];
        float* orow = out + (size_t)gm * 4096 + n0 + tx * 8;
        float4 o0 = make_float4(acc[i][0] + bv_, acc[i][1] + bv_, acc[i][2] + bv_, acc[i][3] + bv_);
        float4 o1 = make_float4(acc[i][4] + bv_, acc[i][5] + bv_, acc[i][6] + bv_, acc[i][7] + bv_);
        *(float4*)orow       = o0;
        *(float4*)(orow + 4) = o1;
    }
}

// =================================================================================
// Generic batched GEMM: C[m,n] = sum_k A[m,k] * B(k,n)
//   TRANSB=false : B is (K x N) row-major
//   TRANSB=true  : B is (N x K) row-major (dot of rows)
// Guards for M/N not multiples of 128 (U_=450). K always multiple of 8; rows of
// A/B always multiples of 4 floats (512 or 4096) => float4 loads safe.
// =================================================================================
template <bool TRANSB>
__global__ void gemm_tpl(const float* __restrict__ Aall, size_t sA,
                         const float* __restrict__ Ball, size_t sB,
                         float* __restrict__ Call, size_t sC,
                         int M, int N, int K)
{
    const float* A  = Aall + (size_t)blockIdx.z * sA;
    const float* Bp = Ball + (size_t)blockIdx.z * sB;
    float*       C  = Call + (size_t)blockIdx.z * sC;

    __shared__ __align__(16) float As[8][128];
    __shared__ __align__(16) float Bs[8][128];

    int tid = threadIdx.x;
    int m0 = blockIdx.y * 128, n0 = blockIdx.x * 128;
    int tx = tid & 15, ty = tid >> 4;

    float acc[8][8];
#pragma unroll
    for (int i = 0; i < 8; i++)
#pragma unroll
        for (int j = 0; j < 8; j++) acc[i][j] = 0.f;

    for (int k0 = 0; k0 < K; k0 += 8) {
        {   // A tile
            int r = tid >> 1, cg = (tid & 1) * 4;
            int gm = m0 + r;
            float4 v = make_float4(0.f, 0.f, 0.f, 0.f);
            if (gm < M) v = *(const float4*)(A + (size_t)gm * K + k0 + cg);
            As[cg + 0][r] = v.x; As[cg + 1][r] = v.y; As[cg + 2][r] = v.z; As[cg + 3][r] = v.w;
        }
        if (TRANSB) {   // B tile from (N x K): Bs[kk][nn] = B[n0+nn][k0+kk]
            int r = tid >> 1, cg = (tid & 1) * 4;
            int gn = n0 + r;
            float4 v = make_float4(0.f, 0.f, 0.f, 0.f);
            if (gn < N) v = *(const float4*)(Bp + (size_t)gn * K + k0 + cg);
            Bs[cg + 0][r] = v.x; Bs[cg + 1][r] = v.y; Bs[cg + 2][r] = v.z; Bs[cg + 3][r] = v.w;
        } else {        // B tile from (K x N)
            int r = tid >> 5, c = (tid & 31) * 4;
            int gk = k0 + r;
            int gn = n0 + c;
            float4 v = make_float4(0.f, 0.f, 0.f, 0.f);
            if (gn + 3 < N) v = *(const float4*)(Bp + (size_t)gk * N + gn);
            Bs[r][c + 0] = v.x; Bs[r][c + 1] = v.y; Bs[r][c + 2] = v.z; Bs[r][c + 3] = v.w;
        }
        __syncthreads();
#pragma unroll
        for (int kk = 0; kk < 8; kk++) {
            float a[8], bb[8];
            *(float4*)(a)      = *(const float4*)&As[kk][ty * 8];
            *(float4*)(a + 4)  = *(const float4*)&As[kk][ty * 8 + 4];
            *(float4*)(bb)     = *(const float4*)&Bs[kk][tx * 8];
            *(float4*)(bb + 4) = *(const float4*)&Bs[kk][tx * 8 + 4];
#pragma unroll
            for (int i = 0; i < 8; i++)
#pragma unroll
                for (int j = 0; j < 8; j++) acc[i][j] += a[i] * bb[j];
        }
        __syncthreads();
    }
#pragma unroll
    for (int i = 0; i < 8; i++) {
        int gm = m0 + ty * 8 + i;
        if (gm >= M) continue;
#pragma unroll
        for (int j = 0; j < 8; j++) {
            int gn = n0 + tx * 8 + j;
            if (gn < N) C[(size_t)gm * N + gn] = acc[i][j];
        }
    }
}

// ---------------- K_sample gather: g_ksamp[b][s][:] = g_k[b][idx[s]][:] --------
__global__ void gather_ksamp(const int* __restrict__ idx)
{
    int b = blockIdx.y, u = blockIdx.x;
    int r = idx[u];
    const float4* s = (const float4*)(g_k + ((size_t)b * L_ + r) * D_);
    float4*       d = (float4*)(g_ksamp + ((size_t)b * U_ + u) * D_);
    d[threadIdx.x] = s[threadIdx.x];
}

// ---------------- M[l] = max_s QKs - sum_s QKs / L  ----------------------------
__global__ void mreduce_kernel()
{
    int b = blockIdx.y;
    int l = blockIdx.x * 8 + (threadIdx.x >> 5);
    int lane = threadIdx.x & 31;
    const float* row = g_scores + ((size_t)b * L_ + l) * U_;
    float mx = -3.0e38f, sm = 0.f;
    for (int s = lane; s < U_; s += 32) { float v = row[s]; mx = fmaxf(mx, v); sm += v; }
#pragma unroll
    for (int o = 16; o; o >>= 1) {
        mx = fmaxf(mx, __shfl_xor_sync(0xffffffffu, mx, o));
        sm += __shfl_xor_sync(0xffffffffu, sm, o);
    }
    if (!lane) g_M[b * L_ + l] = mx - sm * (1.0f / 4096.0f);
}

// ---------------- top-450 per batch: in-smem bitonic sort of 4096 keys ---------
// key = (orderable_f32(M) << 32) | (4095 - l)  -> descending value, then lower
// index first on ties (matches jax.lax.top_k tie-break).
__global__ void topk_kernel()
{
    __shared__ unsigned long long key[4096];
    int b = blockIdx.x;
    const float* m = g_M + b * L_;
    for (int i = threadIdx.x; i < 4096; i += 1024) {
        unsigned u = __float_as_uint(m[i]);
        u = (u & 0x80000000u) ? ~u : (u | 0x80000000u);
        key[i] = ((unsigned long long)u << 32) | (unsigned)(4095 - i);
    }
    __syncthreads();
    for (int k = 2; k <= 4096; k <<= 1) {
        for (int j = k >> 1; j > 0; j >>= 1) {
            for (int i = threadIdx.x; i < 4096; i += 1024) {
                int ixj = i ^ j;
                if (ixj > i) {
                    bool up = ((i & k) == 0);  // ascending overall
                    unsigned long long a = key[i], c = key[ixj];
                    if ((a > c) == up) { key[i] = c; key[ixj] = a; }
                }
            }
            __syncthreads();
        }
    }
    for (int t = threadIdx.x; t < U_; t += 1024) {
        unsigned long long kk = key[4095 - t];          // largest first
        int idx = 4095 - (int)(unsigned)(kk & 0xFFFFFFFFu);
        g_top[b * U_ + t] = idx;
    }
}

// ---------------- Q_sel gather -------------------------------------------------
__global__ void gather_qsel()
{
    int b = blockIdx.y, u = blockIdx.x;
    int r = g_top[b * U_ + u];
    const float4* s = (const float4*)(g_q + ((size_t)b * L_ + r) * D_);
    float4*       d = (float4*)(g_qsel + ((size_t)b * U_ + u) * D_);
    d[threadIdx.x] = s[threadIdx.x];
}

// ---------------- softmax over l (4096) per selected row, scale folded in -----
__global__ void softmax_kernel()
{
    int b = blockIdx.y, u = blockIdx.x;
    float* row = g_scores + ((size_t)b * U_ + (size_t)u) * L_;
    int tid = threadIdx.x;
    int lane = tid & 31, wid = tid >> 5;

    float v[16]; float mx = -3.0e38f;
#pragma unroll
    for (int i = 0; i < 16; i++) {
        float t = row[tid + i * 256] * SCALE_;
        v[i] = t; mx = fmaxf(mx, t);
    }
    __shared__ float red[8];
    __shared__ float bcast;
#pragma unroll
    for (int o = 16; o; o >>= 1) mx = fmaxf(mx, __shfl_xor_sync(0xffffffffu, mx, o));
    if (!lane) red[wid] = mx;
    __syncthreads();
    if (!tid) { float m2 = red[0]; for (int w = 1; w < 8; w++) m2 = fmaxf(m2, red[w]); bcast = m2; }
    __syncthreads();
    mx = bcast;

    float sm = 0.f;
#pragma unroll
    for (int i = 0; i < 16; i++) { v[i] = expf(v[i] - mx); sm += v[i]; }
#pragma unroll
    for (int o = 16; o; o >>= 1) sm += __shfl_xor_sync(0xffffffffu, sm, o);
    __syncthreads();
    if (!lane) red[wid] = sm;
    __syncthreads();
    if (!tid) { float s = red[0]; for (int w = 1; w < 8; w++) s += red[w]; bcast = 1.0f / s; }
    __syncthreads();
    float inv = bcast;
#pragma unroll
    for (int i = 0; i < 16; i++) row[tid + i * 256] = v[i] * inv;
}

// ---------------- V column partial sums (for context mean) ---------------------
__global__ void vmean_part()
{
    int b = blockIdx.y, ch = blockIdx.x;   // 8 chunks of 512 rows
    int d = threadIdx.x;                   // 512 threads
    const float* base = g_v + (size_t)b * L_ * D_ + (size_t)ch * 512 * D_ + d;
    float s = 0.f;
    for (int l = 0; l < 512; l++) s += base[(size_t)l * D_];
    g_part[(b * 8 + ch) * D_ + d] = s;
}

// ---------------- fill output with broadcast mean(V) ---------------------------
__global__ void fill_kernel(float* __restrict__ out)
{
    int b = blockIdx.y;
    int l0 = blockIdx.x * 8;
    int d = threadIdx.x;                   // 512 threads
    float s = 0.f;
#pragma unroll
    for (int c = 0; c < 8; c++) s += g_part[(b * 8 + c) * D_ + d];
    s *= (1.0f / 4096.0f);
    float* o = out + (size_t)b * L_ * D_ + (size_t)l0 * D_ + d;
#pragma unroll
    for (int r = 0; r < 8; r++) o[(size_t)r * D_] = s;
}

// ---------------- scatter upd rows at top-k positions --------------------------
__global__ void scatter_kernel(float* __restrict__ out)
{
    int b = blockIdx.y, u = blockIdx.x;
    int r = g_top[b * U_ + u];
    const float4* s = (const float4*)(g_upd + ((size_t)b * U_ + u) * D_);
    float4*       d = (float4*)(out + ((size_t)b * L_ + r) * D_);
    d[threadIdx.x] = s[threadIdx.x];
}

// =================================================================================
extern "C" void kernel_launch(void* const* d_in, const int* in_sizes, int n_in,
                              void* d_out, int out_size)
{
    const float* in1 = (const float*)d_in[0];
    const float* in2 = (const float*)d_in[1];
    const float* Wq  = (const float*)d_in[2];
    const float* bq  = (const float*)d_in[3];
    const float* Wk  = (const float*)d_in[4];
    const float* bk  = (const float*)d_in[5];
    const float* Wv  = (const float*)d_in[6];
    const float* bv  = (const float*)d_in[7];
    const int*   idx = (const int*)d_in[8];
    float* out = (float*)d_out;

    float *qp, *kp, *vp, *scp, *ksp, *qsp, *upp;
    cudaGetSymbolAddress((void**)&qp,  g_q);
    cudaGetSymbolAddress((void**)&kp,  g_k);
    cudaGetSymbolAddress((void**)&vp,  g_v);
    cudaGetSymbolAddress((void**)&scp, g_scores);
    cudaGetSymbolAddress((void**)&ksp, g_ksamp);
    cudaGetSymbolAddress((void**)&qsp, g_qsel);
    cudaGetSymbolAddress((void**)&upp, g_upd);

    // 1. projections (q,k,v): 48 GEMMs of 512x4096x512
    proj_kernel<<<dim3(32, 4, 48), 256>>>(in1, in2, Wq, bq, Wk, bk, Wv, bv);
    // 2. K_sample gather
    gather_ksamp<<<dim3(U_, B_), 128>>>(idx);
    // 3. QKs = q @ ksamp^T : (4096 x 450 x 512)  -> g_scores (b,l,s)
    gemm_tpl<true><<<dim3(4, 32, B_), 256>>>(qp, (size_t)L_ * D_, ksp, (size_t)U_ * D_,
                                             scp, (size_t)L_ * U_, L_, U_, D_);
    // 4. M = max - sum/L
    mreduce_kernel<<<dim3(512, B_), 256>>>();
    // 5. top-450
    topk_kernel<<<B_, 1024>>>();
    // 6. Q_sel gather
    gather_qsel<<<dim3(U_, B_), 128>>>();
    // 7. scores = Q_sel @ K^T : (450 x 4096 x 512) -> g_scores (b,u,l)
    gemm_tpl<true><<<dim3(32, 4, B_), 256>>>(qsp, (size_t)U_ * D_, kp, (size_t)L_ * D_,
                                             scp, (size_t)U_ * L_, U_, L_, D_);
    // 8. softmax rows (scale folded in)
    softmax_kernel<<<dim3(U_, B_), 256>>>();
    // 9. upd = attn @ V : (450 x 512 x 4096)
    gemm_tpl<false><<<dim3(4, 4, B_), 256>>>(scp, (size_t)U_ * L_, vp, (size_t)L_ * D_,
                                             upp, (size_t)U_ * D_, U_, D_, L_);
    // 10. context mean + broadcast fill + scatter
    vmean_part<<<dim3(8, B_), 512>>>();
    fill_kernel<<<dim3(512, B_), 512>>>(out);
    scatter_kernel<<<dim3(U_, B_), 128>>>(out);
}

// round 3
// speedup vs baseline: 1.1231x; 1.1231x over previous
#include <cuda_runtime.h>
#include <cstdint>
#include <math.h>

#define B_  16
#define L_  4096
#define D_  512
#define U_  450
#define UP_ 512                         // U padded to tile multiple
#define SCALE_ 0.04419417382415922f     // 1/sqrt(512)

// ---------------- scratch (device globals; zero-initialized at module load) ----
__device__ float g_q[(size_t)B_ * L_ * D_];
__device__ float g_k[(size_t)B_ * L_ * D_];
__device__ float g_v[(size_t)B_ * L_ * D_];
__device__ float g_qks [(size_t)B_ * L_ * UP_];   // QKs (b,l,s) padded s->512
__device__ float g_attn[(size_t)B_ * UP_ * L_];   // scores/attn (b,u,l) padded u->512
__device__ float g_ksamp[(size_t)B_ * UP_ * D_];  // rows >=450 stay zero forever
__device__ float g_qsel [(size_t)B_ * UP_ * D_];  // rows >=450 stay zero forever
__device__ float g_upd  [(size_t)B_ * UP_ * D_];
__device__ float g_M[B_ * L_];
__device__ int   g_top[B_ * U_];
__device__ float g_part[B_ * 8 * D_];

// ---------------- helpers -------------------------------------------------------
__device__ __forceinline__ float tf32_rna(float x) {
    uint32_t u; asm("cvt.rna.tf32.f32 %0, %1;" : "=r"(u) : "f"(x));
    return __uint_as_float(u);
}
__device__ __forceinline__ void mma168(float* c, const uint32_t* a, const uint32_t* b) {
    asm volatile(
        "mma.sync.aligned.m16n8k8.row.col.f32.tf32.tf32.f32 "
        "{%0,%1,%2,%3}, {%4,%5,%6,%7}, {%8,%9}, {%0,%1,%2,%3};"
        : "+f"(c[0]), "+f"(c[1]), "+f"(c[2]), "+f"(c[3])
        : "r"(a[0]), "r"(a[1]), "r"(a[2]), "r"(a[3]), "r"(b[0]), "r"(b[1]));
}
// rotation swizzle: 32-float rows, col' = (col + 4*row) & 31  (conflict-free)
__device__ __forceinline__ int swidx(int row, int col) {
    return (row << 5) | ((col + (row << 2)) & 31);
}

// =================================================================================
// Tensor-core GEMM via legacy mma.sync tf32, with optional 3xTF32 split
// (PASSES=3: hi*hi + hi*lo + lo*hi => fp32-class accuracy).
// C[m,n] = sum_k A[m,k] * B(n,k)
//   TRANSB=false : B source is (N x K) row-major
//   TRANSB=true  : B source is (K x N) row-major, rows split at splitK (B1/B2)
// M, N multiples of 128; K multiple of 32. 256 thr, 8 warps (2M x 4N), warp
// tile 64x32, fragments m16n8k8.
// =================================================================================
template <bool TRANSB, int PASSES>
__global__ void __launch_bounds__(256, 1) gemm_mma(
    const float* __restrict__ A, unsigned long long sA, int lda,
    const float* __restrict__ B1, const float* __restrict__ B2,
    unsigned long long sB, int ldb, int splitK,
    float* __restrict__ C, unsigned long long sC, int ldc,
    const float* __restrict__ bias, int K)
{
    extern __shared__ __align__(16) float sm[];
    float* Ah = sm;                                   // 128x32
    float* Bh = sm + 4096;                            // 128x32
    float* Al = sm + 8192;                            // (PASSES==3 only)
    float* Bl = sm + 12288;

    const int tid = threadIdx.x;
    const int lane = tid & 31, wid = tid >> 5;
    const int g = lane >> 2, tig = lane & 3;
    const int wm = wid & 1, wn = wid >> 1;
    const int z = blockIdx.z;
    A  += (size_t)z * sA;
    B1 += (size_t)z * sB;
    B2 += (size_t)z * sB;
    C  += (size_t)z * sC;
    const int m0 = blockIdx.y * 128, n0 = blockIdx.x * 128;

    float acc[16][4];
#pragma unroll
    for (int i = 0; i < 16; i++)
#pragma unroll
        for (int j = 0; j < 4; j++) acc[i][j] = 0.f;

    float4 pA[4], pB[4];
    const int NT = K / 32;

    // ---- prefetch helpers ----
    auto loadA = [&](int kt) {
        const float* Ab = A + (size_t)m0 * lda + kt * 32;
#pragma unroll
        for (int it = 0; it < 4; it++) {
            int task = tid + it * 256;
            int r = task >> 3, cq = task & 7;
            pA[it] = *(const float4*)(Ab + (size_t)r * lda + cq * 4);
        }
    };
    auto loadB = [&](int kt) {
        if (!TRANSB) {
            const float* Bb = B1 + (size_t)n0 * ldb + kt * 32;
#pragma unroll
            for (int it = 0; it < 4; it++) {
                int task = tid + it * 256;
                int r = task >> 3, cq = task & 7;
                pB[it] = *(const float4*)(Bb + (size_t)r * ldb + cq * 4);
            }
        } else {
#pragma unroll
            for (int it = 0; it < 4; it++) {
                int task = tid + it * 256;
                int n = task & 127, q = task >> 7;
                int kb = kt * 32 + q * 4;
                float vv[4];
#pragma unroll
                for (int i = 0; i < 4; i++) {
                    int kk = kb + i;
                    const float* row = (kk < splitK)
                        ? (B1 + (size_t)kk * ldb)
                        : (B2 + (size_t)(kk - splitK) * ldb);
                    vv[i] = row[n0 + n];
                }
                pB[it] = make_float4(vv[0], vv[1], vv[2], vv[3]);
            }
        }
    };
    auto stsAll = [&]() {
#pragma unroll
        for (int it = 0; it < 4; it++) {
            int task = tid + it * 256;
            {   // A
                int r = task >> 3, c0 = (task & 7) * 4;
                float4 v = pA[it];
                float hx = tf32_rna(v.x), hy = tf32_rna(v.y);
                float hz = tf32_rna(v.z), hw = tf32_rna(v.w);
                int idx = swidx(r, c0);
                *(float4*)&Ah[idx] = make_float4(hx, hy, hz, hw);
                if (PASSES == 3)
                    *(float4*)&Al[idx] = make_float4(
                        tf32_rna(v.x - hx), tf32_rna(v.y - hy),
                        tf32_rna(v.z - hz), tf32_rna(v.w - hw));
            }
            {   // B
                int r, c0;
                if (!TRANSB) { r = task >> 3; c0 = (task & 7) * 4; }
                else         { r = task & 127; c0 = (task >> 7) * 4; }
                float4 v = pB[it];
                float hx = tf32_rna(v.x), hy = tf32_rna(v.y);
                float hz = tf32_rna(v.z), hw = tf32_rna(v.w);
                int idx = swidx(r, c0);
                *(float4*)&Bh[idx] = make_float4(hx, hy, hz, hw);
                if (PASSES == 3)
                    *(float4*)&Bl[idx] = make_float4(
                        tf32_rna(v.x - hx), tf32_rna(v.y - hy),
                        tf32_rna(v.z - hz), tf32_rna(v.w - hw));
            }
        }
    };

    loadA(0); loadB(0);
    for (int kt = 0; kt < NT; kt++) {
        stsAll();
        __syncthreads();
        if (kt + 1 < NT) { loadA(kt + 1); loadB(kt + 1); }
#pragma unroll
        for (int ks = 0; ks < 4; ks++) {
            const int k0 = ks * 8;
            uint32_t ah[4][4], bh[4][2];
            uint32_t al[4][4], bl[4][2];
#pragma unroll
            for (int mt = 0; mt < 4; mt++) {
                int r0 = wm * 64 + mt * 16 + g, r1 = r0 + 8;
                ah[mt][0] = __float_as_uint(Ah[swidx(r0, k0 + tig)]);
                ah[mt][1] = __float_as_uint(Ah[swidx(r1, k0 + tig)]);
                ah[mt][2] = __float_as_uint(Ah[swidx(r0, k0 + tig + 4)]);
                ah[mt][3] = __float_as_uint(Ah[swidx(r1, k0 + tig + 4)]);
                if (PASSES == 3) {
                    al[mt][0] = __float_as_uint(Al[swidx(r0, k0 + tig)]);
                    al[mt][1] = __float_as_uint(Al[swidx(r1, k0 + tig)]);
                    al[mt][2] = __float_as_uint(Al[swidx(r0, k0 + tig + 4)]);
                    al[mt][3] = __float_as_uint(Al[swidx(r1, k0 + tig + 4)]);
                }
            }
#pragma unroll
            for (int nt = 0; nt < 4; nt++) {
                int rn = wn * 32 + nt * 8 + g;
                bh[nt][0] = __float_as_uint(Bh[swidx(rn, k0 + tig)]);
                bh[nt][1] = __float_as_uint(Bh[swidx(rn, k0 + tig + 4)]);
                if (PASSES == 3) {
                    bl[nt][0] = __float_as_uint(Bl[swidx(rn, k0 + tig)]);
                    bl[nt][1] = __float_as_uint(Bl[swidx(rn, k0 + tig + 4)]);
                }
            }
#pragma unroll
            for (int mt = 0; mt < 4; mt++)
#pragma unroll
                for (int nt = 0; nt < 4; nt++) {
                    mma168(acc[mt * 4 + nt], ah[mt], bh[nt]);
                    if (PASSES == 3) {
                        mma168(acc[mt * 4 + nt], ah[mt], bl[nt]);
                        mma168(acc[mt * 4 + nt], al[mt], bh[nt]);
                    }
                }
        }
        __syncthreads();
    }

    // ---- epilogue ----
#pragma unroll
    for (int mt = 0; mt < 4; mt++) {
        int r0 = m0 + wm * 64 + mt * 16 + g;
        float b0 = bias ? bias[r0] : 0.f;
        float b1 = bias ? bias[r0 + 8] : 0.f;
#pragma unroll
        for (int nt = 0; nt < 4; nt++) {
            int cc = n0 + wn * 32 + nt * 8 + 2 * tig;
            float* c = acc[mt * 4 + nt];
            *(float2*)(C + (size_t)r0 * ldc + cc) = make_float2(c[0] + b0, c[1] + b0);
            *(float2*)(C + (size_t)(r0 + 8) * ldc + cc) = make_float2(c[2] + b1, c[3] + b1);
        }
    }
}

// ---------------- K_sample gather (into zero-padded buffer) --------------------
__global__ void gather_ksamp(const int* __restrict__ idx)
{
    int b = blockIdx.y, u = blockIdx.x;
    int r = idx[u];
    const float4* s = (const float4*)(g_k + ((size_t)b * L_ + r) * D_);
    float4*       d = (float4*)(g_ksamp + ((size_t)b * UP_ + u) * D_);
    d[threadIdx.x] = s[threadIdx.x];
}

// ---------------- M[l] = max_s QKs - sum_s QKs / L  ----------------------------
__global__ void mreduce_kernel()
{
    int b = blockIdx.y;
    int l = blockIdx.x * 8 + (threadIdx.x >> 5);
    int lane = threadIdx.x & 31;
    const float* row = g_qks + ((size_t)b * L_ + l) * UP_;
    float mx = -3.0e38f, sm = 0.f;
    for (int s = lane; s < U_; s += 32) { float v = row[s]; mx = fmaxf(mx, v); sm += v; }
#pragma unroll
    for (int o = 16; o; o >>= 1) {
        mx = fmaxf(mx, __shfl_xor_sync(0xffffffffu, mx, o));
        sm += __shfl_xor_sync(0xffffffffu, sm, o);
    }
    if (!lane) g_M[b * L_ + l] = mx - sm * (1.0f / 4096.0f);
}

// ---------------- top-450 via in-smem bitonic sort (tie-break = lower index) ---
__global__ void topk_kernel()
{
    __shared__ unsigned long long key[4096];
    int b = blockIdx.x;
    const float* m = g_M + b * L_;
    for (int i = threadIdx.x; i < 4096; i += 1024) {
        unsigned u = __float_as_uint(m[i]);
        u = (u & 0x80000000u) ? ~u : (u | 0x80000000u);
        key[i] = ((unsigned long long)u << 32) | (unsigned)(4095 - i);
    }
    __syncthreads();
    for (int k = 2; k <= 4096; k <<= 1) {
        for (int j = k >> 1; j > 0; j >>= 1) {
            for (int i = threadIdx.x; i < 4096; i += 1024) {
                int ixj = i ^ j;
                if (ixj > i) {
                    bool up = ((i & k) == 0);
                    unsigned long long a = key[i], c = key[ixj];
                    if ((a > c) == up) { key[i] = c; key[ixj] = a; }
                }
            }
            __syncthreads();
        }
    }
    for (int t = threadIdx.x; t < U_; t += 1024) {
        unsigned long long kk = key[4095 - t];
        g_top[b * U_ + t] = 4095 - (int)(unsigned)(kk & 0xFFFFFFFFu);
    }
}

// ---------------- Q_sel gather -------------------------------------------------
__global__ void gather_qsel()
{
    int b = blockIdx.y, u = blockIdx.x;
    int r = g_top[b * U_ + u];
    const float4* s = (const float4*)(g_q + ((size_t)b * L_ + r) * D_);
    float4*       d = (float4*)(g_qsel + ((size_t)b * UP_ + u) * D_);
    d[threadIdx.x] = s[threadIdx.x];
}

// ---------------- softmax over l per selected row (scale folded in) ------------
__global__ void softmax_kernel()
{
    int b = blockIdx.y, u = blockIdx.x;
    float* row = g_attn + ((size_t)b * UP_ + (size_t)u) * L_;
    int tid = threadIdx.x;
    int lane = tid & 31, wid = tid >> 5;

    float v[16]; float mx = -3.0e38f;
#pragma unroll
    for (int i = 0; i < 16; i++) {
        float t = row[tid + i * 256] * SCALE_;
        v[i] = t; mx = fmaxf(mx, t);
    }
    __shared__ float red[8];
    __shared__ float bcast;
#pragma unroll
    for (int o = 16; o; o >>= 1) mx = fmaxf(mx, __shfl_xor_sync(0xffffffffu, mx, o));
    if (!lane) red[wid] = mx;
    __syncthreads();
    if (!tid) { float m2 = red[0]; for (int w = 1; w < 8; w++) m2 = fmaxf(m2, red[w]); bcast = m2; }
    __syncthreads();
    mx = bcast;

    float sm = 0.f;
#pragma unroll
    for (int i = 0; i < 16; i++) { v[i] = expf(v[i] - mx); sm += v[i]; }
#pragma unroll
    for (int o = 16; o; o >>= 1) sm += __shfl_xor_sync(0xffffffffu, sm, o);
    __syncthreads();
    if (!lane) red[wid] = sm;
    __syncthreads();
    if (!tid) { float s = red[0]; for (int w = 1; w < 8; w++) s += red[w]; bcast = 1.0f / s; }
    __syncthreads();
    float inv = bcast;
#pragma unroll
    for (int i = 0; i < 16; i++) row[tid + i * 256] = v[i] * inv;
}

// ---------------- V column partial sums ---------------------------------------
__global__ void vmean_part()
{
    int b = blockIdx.y, ch = blockIdx.x;
    int d = threadIdx.x;
    const float* base = g_v + (size_t)b * L_ * D_ + (size_t)ch * 512 * D_ + d;
    float s = 0.f;
    for (int l = 0; l < 512; l++) s += base[(size_t)l * D_];
    g_part[(b * 8 + ch) * D_ + d] = s;
}

// ---------------- broadcast mean(V) fill ---------------------------------------
__global__ void fill_kernel(float* __restrict__ out)
{
    int b = blockIdx.y;
    int l0 = blockIdx.x * 8;
    int d = threadIdx.x;
    float s = 0.f;
#pragma unroll
    for (int c = 0; c < 8; c++) s += g_part[(b * 8 + c) * D_ + d];
    s *= (1.0f / 4096.0f);
    float* o = out + (size_t)b * L_ * D_ + (size_t)l0 * D_ + d;
#pragma unroll
    for (int r = 0; r < 8; r++) o[(size_t)r * D_] = s;
}

// ---------------- scatter upd rows ---------------------------------------------
__global__ void scatter_kernel(float* __restrict__ out)
{
    int b = blockIdx.y, u = blockIdx.x;
    int r = g_top[b * U_ + u];
    const float4* s = (const float4*)(g_upd + ((size_t)b * UP_ + u) * D_);
    float4*       d = (float4*)(out + ((size_t)b * L_ + r) * D_);
    d[threadIdx.x] = s[threadIdx.x];
}

// =================================================================================
#define SM3 65536
#define SM1 32768

extern "C" void kernel_launch(void* const* d_in, const int* in_sizes, int n_in,
                              void* d_out, int out_size)
{
    const float* in1 = (const float*)d_in[0];
    const float* in2 = (const float*)d_in[1];
    const float* Wq  = (const float*)d_in[2];
    const float* bq  = (const float*)d_in[3];
    const float* Wk  = (const float*)d_in[4];
    const float* bk  = (const float*)d_in[5];
    const float* Wv  = (const float*)d_in[6];
    const float* bv  = (const float*)d_in[7];
    const int*   idx = (const int*)d_in[8];
    float* out = (float*)d_out;

    float *qp, *kp, *vp, *qksp, *attnp, *ksp, *qsp, *upp;
    cudaGetSymbolAddress((void**)&qp,   g_q);
    cudaGetSymbolAddress((void**)&kp,   g_k);
    cudaGetSymbolAddress((void**)&vp,   g_v);
    cudaGetSymbolAddress((void**)&qksp, g_qks);
    cudaGetSymbolAddress((void**)&attnp,g_attn);
    cudaGetSymbolAddress((void**)&ksp,  g_ksamp);
    cudaGetSymbolAddress((void**)&qsp,  g_qsel);
    cudaGetSymbolAddress((void**)&upp,  g_upd);

    cudaFuncSetAttribute(gemm_mma<true, 3>,  cudaFuncAttributeMaxDynamicSharedMemorySize, SM3);
    cudaFuncSetAttribute(gemm_mma<true, 1>,  cudaFuncAttributeMaxDynamicSharedMemorySize, SM3);
    cudaFuncSetAttribute(gemm_mma<false, 3>, cudaFuncAttributeMaxDynamicSharedMemorySize, SM3);
    cudaFuncSetAttribute(gemm_mma<false, 1>, cudaFuncAttributeMaxDynamicSharedMemorySize, SM3);

    const unsigned long long sX   = (unsigned long long)256 * 4096;
    const unsigned long long sQKV = (unsigned long long)L_ * D_;

    // 1. projections: C(512 x 4096) = W @ X, X (512x4096) split across in1/in2
    //    q,k need fp32 accuracy (selection path) -> 3xTF32; v tolerant -> 1x.
    gemm_mma<true, 3><<<dim3(32, 4, B_), 256, SM3>>>(
        Wq, 0ull, 512, in1, in2, sX, 4096, 256, qp, sQKV, 4096, bq, 512);
    gemm_mma<true, 3><<<dim3(32, 4, B_), 256, SM3>>>(
        Wk, 0ull, 512, in1, in2, sX, 4096, 256, kp, sQKV, 4096, bk, 512);
    gemm_mma<true, 1><<<dim3(32, 4, B_), 256, SM1>>>(
        Wv, 0ull, 512, in1, in2, sX, 4096, 256, vp, sQKV, 4096, bv, 512);

    // 2. K_sample gather (padded rows remain zero)
    gather_ksamp<<<dim3(U_, B_), 128>>>(idx);

    // 3. QKs = q @ ksamp^T : (4096 x 512pad x 512), selection path -> 3x
    gemm_mma<false, 3><<<dim3(4, 32, B_), 256, SM3>>>(
        qp, sQKV, 512, ksp, ksp, (unsigned long long)UP_ * D_, 512, 512,
        qksp, (unsigned long long)L_ * UP_, UP_, nullptr, 512);

    // 4. M reduce    5. top-450    6. Q_sel gather
    mreduce_kernel<<<dim3(512, B_), 256>>>();
    topk_kernel<<<B_, 1024>>>();
    gather_qsel<<<dim3(U_, B_), 128>>>();

    // 7. scores = Q_sel @ K^T : (512pad x 4096 x 512), softmax-tolerant -> 1x
    gemm_mma<false, 1><<<dim3(32, 4, B_), 256, SM1>>>(
        qsp, (unsigned long long)UP_ * D_, 512, kp, kp, sQKV, 512, 512,
        attnp, (unsigned long long)UP_ * L_, 4096, nullptr, 512);

    // 8. softmax
    softmax_kernel<<<dim3(U_, B_), 256>>>();

    // 9. upd = attn @ V : (512pad x 512 x 4096), V is (K x N) -> TRANSB, 1x
    gemm_mma<true, 1><<<dim3(4, 4, B_), 256, SM1>>>(
        attnp, (unsigned long long)UP_ * L_, 4096, vp, vp, sQKV, 512, 4096,
        upp, (unsigned long long)UP_ * D_, 512, nullptr, 4096);

    // 10. mean fill + scatter
    vmean_part<<<dim3(8, B_), 512>>>();
    fill_kernel<<<dim3(512, B_), 512>>>(out);
    scatter_kernel<<<dim3(U_, B_), 128>>>(out);
}

// round 4
// speedup vs baseline: 2.2413x; 1.9957x over previous
#include <cuda_runtime.h>
#include <cuda_fp16.h>
#include <cstdint>
#include <math.h>

#define B_  16
#define L_  4096
#define D_  512
#define U_  450
#define UP_ 512
#define SCALE_ 0.04419417382415922f     // 1/sqrt(512)
typedef unsigned long long ull;

// ---------------- scratch -------------------------------------------------------
__device__ float g_q[(size_t)B_ * L_ * D_];
__device__ float g_k[(size_t)B_ * L_ * D_];
__device__ float g_v[(size_t)B_ * L_ * D_];
__device__ float g_qks [(size_t)B_ * L_ * UP_];
__device__ float g_attn[(size_t)B_ * UP_ * L_];
__device__ float g_ksamp[(size_t)B_ * UP_ * D_];  // rows >=450 stay zero
__device__ float g_qsel [(size_t)B_ * UP_ * D_];
__device__ float g_upd  [(size_t)B_ * UP_ * D_];
__device__ float g_M[B_ * L_];
__device__ int   g_top[B_ * U_];
__device__ float g_part[B_ * 8 * D_];

// ---------------- helpers -------------------------------------------------------
__device__ __forceinline__ float tf32_rna(float x) {
    uint32_t u; asm("cvt.rna.tf32.f32 %0, %1;" : "=r"(u) : "f"(x));
    return __uint_as_float(u);
}
__device__ __forceinline__ void mma168(float* c, const uint32_t* a, const uint32_t* b) {
    asm volatile(
        "mma.sync.aligned.m16n8k8.row.col.f32.tf32.tf32.f32 "
        "{%0,%1,%2,%3}, {%4,%5,%6,%7}, {%8,%9}, {%0,%1,%2,%3};"
        : "+f"(c[0]), "+f"(c[1]), "+f"(c[2]), "+f"(c[3])
        : "r"(a[0]), "r"(a[1]), "r"(a[2]), "r"(a[3]), "r"(b[0]), "r"(b[1]));
}
__device__ __forceinline__ void mma16816(float* c, const uint32_t* a, const uint32_t* b) {
    asm volatile(
        "mma.sync.aligned.m16n8k16.row.col.f32.f16.f16.f32 "
        "{%0,%1,%2,%3}, {%4,%5,%6,%7}, {%8,%9}, {%0,%1,%2,%3};"
        : "+f"(c[0]), "+f"(c[1]), "+f"(c[2]), "+f"(c[3])
        : "r"(a[0]), "r"(a[1]), "r"(a[2]), "r"(a[3]), "r"(b[0]), "r"(b[1]));
}
// tf32 smem rotation swizzle: 32-float rows
__device__ __forceinline__ int swidx(int row, int col) {
    return (row << 5) | ((col + (row << 2)) & 31);
}
// fp16 smem XOR swizzle: rows of 16 uint32 (half2 words)
__device__ __forceinline__ int hwidx(int row, int w) {
    return (row << 4) | (w ^ ((row << 1) & 14));
}
__device__ __forceinline__ uint32_t packh2(float x, float y) {
    __half2 h = __floats2half2_rn(x, y);
    return *(uint32_t*)&h;
}
__device__ __forceinline__ float2 unpackh2f(uint32_t u) {
    __half2 h = *(__half2*)&u;
    return __half22float2(h);
}

// =================================================================================
// fp16 mma.sync GEMM, optional 2-way split (PASSES=3: hh+hl+lh, ~fp32 accuracy).
// C[m,n] = sum_k A[m,k]*B(n,k).  A pre-scaled by ascale (epilogue * 1/ascale).
//   TRANSB=false : B source is (N x K) row-major
//   TRANSB=true  : B source is (K x N) row-major, rows split at splitK (B1/B2)
// 256 thr, 8 warps (2Mx4N), block 128x128, K-tile 32 halves.
// =================================================================================
template <bool TRANSB, int PASSES>
__global__ void __launch_bounds__(256, 1) gemm_h(
    const float* __restrict__ A, ull sA, int lda,
    const float* __restrict__ B1, const float* __restrict__ B2,
    ull sB, int ldb, int splitK,
    float* __restrict__ C, ull sC, int ldc,
    const float* __restrict__ bias, int K, float ascale, float inv_ascale)
{
    __shared__ __align__(16) uint32_t smh[(PASSES == 3 ? 4 : 2) * 2048];
    uint32_t* Ah = smh;                      // 128 x 16 words
    uint32_t* Bh = smh + 2048;
    uint32_t* Al = (PASSES == 3) ? smh + 4096 : smh;
    uint32_t* Bl = (PASSES == 3) ? smh + 6144 : smh;

    const int tid = threadIdx.x;
    const int lane = tid & 31, wid = tid >> 5;
    const int g = lane >> 2, tig = lane & 3;
    const int wm = wid & 1, wn = wid >> 1;
    const int z = blockIdx.z;
    A  += (size_t)z * sA;
    B1 += (size_t)z * sB;
    B2 += (size_t)z * sB;
    C  += (size_t)z * sC;
    const int m0 = blockIdx.y * 128, n0 = blockIdx.x * 128;

    float acc[16][4];
#pragma unroll
    for (int i = 0; i < 16; i++)
#pragma unroll
        for (int j = 0; j < 4; j++) acc[i][j] = 0.f;

    float4 pA[4], pB[4];
    const int NT = K / 32;

    auto loadA = [&](int kt) {
        const float* Ab = A + (size_t)m0 * lda + kt * 32;
#pragma unroll
        for (int it = 0; it < 4; it++) {
            int task = tid + it * 256;
            int r = task >> 3, cq = task & 7;
            pA[it] = *(const float4*)(Ab + (size_t)r * lda + cq * 4);
        }
    };
    auto loadB = [&](int kt) {
        if (!TRANSB) {
            const float* Bb = B1 + (size_t)n0 * ldb + kt * 32;
#pragma unroll
            for (int it = 0; it < 4; it++) {
                int task = tid + it * 256;
                int r = task >> 3, cq = task & 7;
                pB[it] = *(const float4*)(Bb + (size_t)r * ldb + cq * 4);
            }
        } else {
#pragma unroll
            for (int it = 0; it < 4; it++) {
                int task = tid + it * 256;
                int n = task & 127, q = task >> 7;
                int kb = kt * 32 + q * 4;
                float vv[4];
#pragma unroll
                for (int i = 0; i < 4; i++) {
                    int kk = kb + i;
                    const float* row = (kk < splitK)
                        ? (B1 + (size_t)kk * ldb)
                        : (B2 + (size_t)(kk - splitK) * ldb);
                    vv[i] = row[n0 + n];
                }
                pB[it] = make_float4(vv[0], vv[1], vv[2], vv[3]);
            }
        }
    };
    auto stsAll = [&]() {
#pragma unroll
        for (int it = 0; it < 4; it++) {
            int task = tid + it * 256;
            {   // A (scaled)
                int r = task >> 3, cq = task & 7;
                float4 v = pA[it];
                v.x *= ascale; v.y *= ascale; v.z *= ascale; v.w *= ascale;
                uint32_t h0 = packh2(v.x, v.y), h1 = packh2(v.z, v.w);
                int w = (2 * cq) ^ ((r << 1) & 14);
                *(uint2*)&Ah[r * 16 + w] = make_uint2(h0, h1);
                if (PASSES == 3) {
                    float2 f0 = unpackh2f(h0), f1 = unpackh2f(h1);
                    *(uint2*)&Al[r * 16 + w] = make_uint2(
                        packh2(v.x - f0.x, v.y - f0.y),
                        packh2(v.z - f1.x, v.w - f1.y));
                }
            }
            {   // B
                int r, cq;
                if (!TRANSB) { r = task >> 3; cq = task & 7; }
                else         { r = task & 127; cq = task >> 7; }
                float4 v = pB[it];
                uint32_t h0 = packh2(v.x, v.y), h1 = packh2(v.z, v.w);
                int w = (2 * cq) ^ ((r << 1) & 14);
                *(uint2*)&Bh[r * 16 + w] = make_uint2(h0, h1);
                if (PASSES == 3) {
                    float2 f0 = unpackh2f(h0), f1 = unpackh2f(h1);
                    *(uint2*)&Bl[r * 16 + w] = make_uint2(
                        packh2(v.x - f0.x, v.y - f0.y),
                        packh2(v.z - f1.x, v.w - f1.y));
                }
            }
        }
    };

    loadA(0); loadB(0);
    for (int kt = 0; kt < NT; kt++) {
        stsAll();
        __syncthreads();
        if (kt + 1 < NT) { loadA(kt + 1); loadB(kt + 1); }
#pragma unroll
        for (int ks = 0; ks < 2; ks++) {           // two k=16 steps per k-tile 32
            const int wb = ks * 8;
            uint32_t ah[4][4], bh[4][2], al[4][4], bl[4][2];
#pragma unroll
            for (int mt = 0; mt < 4; mt++) {
                int r0 = wm * 64 + mt * 16 + g, r1 = r0 + 8;
                ah[mt][0] = Ah[hwidx(r0, wb + tig)];
                ah[mt][1] = Ah[hwidx(r1, wb + tig)];
                ah[mt][2] = Ah[hwidx(r0, wb + tig + 4)];
                ah[mt][3] = Ah[hwidx(r1, wb + tig + 4)];
                if (PASSES == 3) {
                    al[mt][0] = Al[hwidx(r0, wb + tig)];
                    al[mt][1] = Al[hwidx(r1, wb + tig)];
                    al[mt][2] = Al[hwidx(r0, wb + tig + 4)];
                    al[mt][3] = Al[hwidx(r1, wb + tig + 4)];
                }
            }
#pragma unroll
            for (int nt = 0; nt < 4; nt++) {
                int rn = wn * 32 + nt * 8 + g;
                bh[nt][0] = Bh[hwidx(rn, wb + tig)];
                bh[nt][1] = Bh[hwidx(rn, wb + tig + 4)];
                if (PASSES == 3) {
                    bl[nt][0] = Bl[hwidx(rn, wb + tig)];
                    bl[nt][1] = Bl[hwidx(rn, wb + tig + 4)];
                }
            }
#pragma unroll
            for (int mt = 0; mt < 4; mt++)
#pragma unroll
                for (int nt = 0; nt < 4; nt++) {
                    mma16816(acc[mt * 4 + nt], ah[mt], bh[nt]);
                    if (PASSES == 3) {
                        mma16816(acc[mt * 4 + nt], ah[mt], bl[nt]);
                        mma16816(acc[mt * 4 + nt], al[mt], bh[nt]);
                    }
                }
        }
        __syncthreads();
    }

#pragma unroll
    for (int mt = 0; mt < 4; mt++) {
        int r0 = m0 + wm * 64 + mt * 16 + g;
        float b0 = bias ? bias[r0] : 0.f;
        float b1 = bias ? bias[r0 + 8] : 0.f;
#pragma unroll
        for (int nt = 0; nt < 4; nt++) {
            int cc = n0 + wn * 32 + nt * 8 + 2 * tig;
            float* c = acc[mt * 4 + nt];
            *(float2*)(C + (size_t)r0 * ldc + cc) =
                make_float2(c[0] * inv_ascale + b0, c[1] * inv_ascale + b0);
            *(float2*)(C + (size_t)(r0 + 8) * ldc + cc) =
                make_float2(c[2] * inv_ascale + b1, c[3] * inv_ascale + b1);
        }
    }
}

// =================================================================================
// tf32 3x GEMM (selection-critical QKs). TRANSB=false only: B is (N x K) rows.
// =================================================================================
template <int PASSES>
__global__ void __launch_bounds__(256, 1) gemm_mma(
    const float* __restrict__ A, ull sA, int lda,
    const float* __restrict__ B1, ull sB, int ldb,
    float* __restrict__ C, ull sC, int ldc, int K)
{
    extern __shared__ __align__(16) float sm[];
    float* Ah = sm;
    float* Bh = sm + 4096;
    float* Al = sm + 8192;
    float* Bl = sm + 12288;

    const int tid = threadIdx.x;
    const int lane = tid & 31, wid = tid >> 5;
    const int g = lane >> 2, tig = lane & 3;
    const int wm = wid & 1, wn = wid >> 1;
    const int z = blockIdx.z;
    A  += (size_t)z * sA;
    B1 += (size_t)z * sB;
    C  += (size_t)z * sC;
    const int m0 = blockIdx.y * 128, n0 = blockIdx.x * 128;

    float acc[16][4];
#pragma unroll
    for (int i = 0; i < 16; i++)
#pragma unroll
        for (int j = 0; j < 4; j++) acc[i][j] = 0.f;

    float4 pA[4], pB[4];
    const int NT = K / 32;

    auto loadA = [&](int kt) {
        const float* Ab = A + (size_t)m0 * lda + kt * 32;
#pragma unroll
        for (int it = 0; it < 4; it++) {
            int task = tid + it * 256;
            int r = task >> 3, cq = task & 7;
            pA[it] = *(const float4*)(Ab + (size_t)r * lda + cq * 4);
        }
    };
    auto loadB = [&](int kt) {
        const float* Bb = B1 + (size_t)n0 * ldb + kt * 32;
#pragma unroll
        for (int it = 0; it < 4; it++) {
            int task = tid + it * 256;
            int r = task >> 3, cq = task & 7;
            pB[it] = *(const float4*)(Bb + (size_t)r * ldb + cq * 4);
        }
    };
    auto stsAll = [&]() {
#pragma unroll
        for (int it = 0; it < 4; it++) {
            int task = tid + it * 256;
            int r = task >> 3, c0 = (task & 7) * 4;
            {
                float4 v = pA[it];
                float hx = tf32_rna(v.x), hy = tf32_rna(v.y);
                float hz = tf32_rna(v.z), hw = tf32_rna(v.w);
                int idx = swidx(r, c0);
                *(float4*)&Ah[idx] = make_float4(hx, hy, hz, hw);
                *(float4*)&Al[idx] = make_float4(
                    tf32_rna(v.x - hx), tf32_rna(v.y - hy),
                    tf32_rna(v.z - hz), tf32_rna(v.w - hw));
            }
            {
                float4 v = pB[it];
                float hx = tf32_rna(v.x), hy = tf32_rna(v.y);
                float hz = tf32_rna(v.z), hw = tf32_rna(v.w);
                int idx = swidx(r, c0);
                *(float4*)&Bh[idx] = make_float4(hx, hy, hz, hw);
                *(float4*)&Bl[idx] = make_float4(
                    tf32_rna(v.x - hx), tf32_rna(v.y - hy),
                    tf32_rna(v.z - hz), tf32_rna(v.w - hw));
            }
        }
    };

    loadA(0); loadB(0);
    for (int kt = 0; kt < NT; kt++) {
        stsAll();
        __syncthreads();
        if (kt + 1 < NT) { loadA(kt + 1); loadB(kt + 1); }
#pragma unroll
        for (int ks = 0; ks < 4; ks++) {
            const int k0 = ks * 8;
            uint32_t ah[4][4], bh[4][2], al[4][4], bl[4][2];
#pragma unroll
            for (int mt = 0; mt < 4; mt++) {
                int r0 = wm * 64 + mt * 16 + g, r1 = r0 + 8;
                ah[mt][0] = __float_as_uint(Ah[swidx(r0, k0 + tig)]);
                ah[mt][1] = __float_as_uint(Ah[swidx(r1, k0 + tig)]);
                ah[mt][2] = __float_as_uint(Ah[swidx(r0, k0 + tig + 4)]);
                ah[mt][3] = __float_as_uint(Ah[swidx(r1, k0 + tig + 4)]);
                al[mt][0] = __float_as_uint(Al[swidx(r0, k0 + tig)]);
                al[mt][1] = __float_as_uint(Al[swidx(r1, k0 + tig)]);
                al[mt][2] = __float_as_uint(Al[swidx(r0, k0 + tig + 4)]);
                al[mt][3] = __float_as_uint(Al[swidx(r1, k0 + tig + 4)]);
            }
#pragma unroll
            for (int nt = 0; nt < 4; nt++) {
                int rn = wn * 32 + nt * 8 + g;
                bh[nt][0] = __float_as_uint(Bh[swidx(rn, k0 + tig)]);
                bh[nt][1] = __float_as_uint(Bh[swidx(rn, k0 + tig + 4)]);
                bl[nt][0] = __float_as_uint(Bl[swidx(rn, k0 + tig)]);
                bl[nt][1] = __float_as_uint(Bl[swidx(rn, k0 + tig + 4)]);
            }
#pragma unroll
            for (int mt = 0; mt < 4; mt++)
#pragma unroll
                for (int nt = 0; nt < 4; nt++) {
                    mma168(acc[mt * 4 + nt], ah[mt], bh[nt]);
                    mma168(acc[mt * 4 + nt], ah[mt], bl[nt]);
                    mma168(acc[mt * 4 + nt], al[mt], bh[nt]);
                }
        }
        __syncthreads();
    }

#pragma unroll
    for (int mt = 0; mt < 4; mt++) {
        int r0 = m0 + wm * 64 + mt * 16 + g;
#pragma unroll
        for (int nt = 0; nt < 4; nt++) {
            int cc = n0 + wn * 32 + nt * 8 + 2 * tig;
            float* c = acc[mt * 4 + nt];
            *(float2*)(C + (size_t)r0 * ldc + cc) = make_float2(c[0], c[1]);
            *(float2*)(C + (size_t)(r0 + 8) * ldc + cc) = make_float2(c[2], c[3]);
        }
    }
}

// ---------------- small kernels (unchanged) ------------------------------------
__global__ void gather_ksamp(const int* __restrict__ idx)
{
    int b = blockIdx.y, u = blockIdx.x;
    int r = idx[u];
    const float4* s = (const float4*)(g_k + ((size_t)b * L_ + r) * D_);
    float4*       d = (float4*)(g_ksamp + ((size_t)b * UP_ + u) * D_);
    d[threadIdx.x] = s[threadIdx.x];
}

__global__ void mreduce_kernel()
{
    int b = blockIdx.y;
    int l = blockIdx.x * 8 + (threadIdx.x >> 5);
    int lane = threadIdx.x & 31;
    const float* row = g_qks + ((size_t)b * L_ + l) * UP_;
    float mx = -3.0e38f, sm = 0.f;
    for (int s = lane; s < U_; s += 32) { float v = row[s]; mx = fmaxf(mx, v); sm += v; }
#pragma unroll
    for (int o = 16; o; o >>= 1) {
        mx = fmaxf(mx, __shfl_xor_sync(0xffffffffu, mx, o));
        sm += __shfl_xor_sync(0xffffffffu, sm, o);
    }
    if (!lane) g_M[b * L_ + l] = mx - sm * (1.0f / 4096.0f);
}

__global__ void topk_kernel()
{
    __shared__ unsigned long long key[4096];
    int b = blockIdx.x;
    const float* m = g_M + b * L_;
    for (int i = threadIdx.x; i < 4096; i += 1024) {
        unsigned u = __float_as_uint(m[i]);
        u = (u & 0x80000000u) ? ~u : (u | 0x80000000u);
        key[i] = ((unsigned long long)u << 32) | (unsigned)(4095 - i);
    }
    __syncthreads();
    for (int k = 2; k <= 4096; k <<= 1) {
        for (int j = k >> 1; j > 0; j >>= 1) {
            for (int i = threadIdx.x; i < 4096; i += 1024) {
                int ixj = i ^ j;
                if (ixj > i) {
                    bool up = ((i & k) == 0);
                    unsigned long long a = key[i], c = key[ixj];
                    if ((a > c) == up) { key[i] = c; key[ixj] = a; }
                }
            }
            __syncthreads();
        }
    }
    for (int t = threadIdx.x; t < U_; t += 1024) {
        unsigned long long kk = key[4095 - t];
        g_top[b * U_ + t] = 4095 - (int)(unsigned)(kk & 0xFFFFFFFFu);
    }
}

__global__ void gather_qsel()
{
    int b = blockIdx.y, u = blockIdx.x;
    int r = g_top[b * U_ + u];
    const float4* s = (const float4*)(g_q + ((size_t)b * L_ + r) * D_);
    float4*       d = (float4*)(g_qsel + ((size_t)b * UP_ + u) * D_);
    d[threadIdx.x] = s[threadIdx.x];
}

__global__ void softmax_kernel()
{
    int b = blockIdx.y, u = blockIdx.x;
    float* row = g_attn + ((size_t)b * UP_ + (size_t)u) * L_;
    int tid = threadIdx.x;
    int lane = tid & 31, wid = tid >> 5;

    float v[16]; float mx = -3.0e38f;
#pragma unroll
    for (int i = 0; i < 16; i++) {
        float t = row[tid + i * 256] * SCALE_;
        v[i] = t; mx = fmaxf(mx, t);
    }
    __shared__ float red[8];
    __shared__ float bcast;
#pragma unroll
    for (int o = 16; o; o >>= 1) mx = fmaxf(mx, __shfl_xor_sync(0xffffffffu, mx, o));
    if (!lane) red[wid] = mx;
    __syncthreads();
    if (!tid) { float m2 = red[0]; for (int w = 1; w < 8; w++) m2 = fmaxf(m2, red[w]); bcast = m2; }
    __syncthreads();
    mx = bcast;

    float sm = 0.f;
#pragma unroll
    for (int i = 0; i < 16; i++) { v[i] = expf(v[i] - mx); sm += v[i]; }
#pragma unroll
    for (int o = 16; o; o >>= 1) sm += __shfl_xor_sync(0xffffffffu, sm, o);
    __syncthreads();
    if (!lane) red[wid] = sm;
    __syncthreads();
    if (!tid) { float s = red[0]; for (int w = 1; w < 8; w++) s += red[w]; bcast = 1.0f / s; }
    __syncthreads();
    float inv = bcast;
#pragma unroll
    for (int i = 0; i < 16; i++) row[tid + i * 256] = v[i] * inv;
}

__global__ void vmean_part()
{
    int b = blockIdx.y, ch = blockIdx.x;
    int d = threadIdx.x;
    const float* base = g_v + (size_t)b * L_ * D_ + (size_t)ch * 512 * D_ + d;
    float s = 0.f;
    for (int l = 0; l < 512; l++) s += base[(size_t)l * D_];
    g_part[(b * 8 + ch) * D_ + d] = s;
}

__global__ void fill_kernel(float* __restrict__ out)
{
    int b = blockIdx.y;
    int l0 = blockIdx.x * 8;
    int d = threadIdx.x;
    float s = 0.f;
#pragma unroll
    for (int c = 0; c < 8; c++) s += g_part[(b * 8 + c) * D_ + d];
    s *= (1.0f / 4096.0f);
    float* o = out + (size_t)b * L_ * D_ + (size_t)l0 * D_ + d;
#pragma unroll
    for (int r = 0; r < 8; r++) o[(size_t)r * D_] = s;
}

__global__ void scatter_kernel(float* __restrict__ out)
{
    int b = blockIdx.y, u = blockIdx.x;
    int r = g_top[b * U_ + u];
    const float4* s = (const float4*)(g_upd + ((size_t)b * UP_ + u) * D_);
    float4*       d = (float4*)(out + ((size_t)b * L_ + r) * D_);
    d[threadIdx.x] = s[threadIdx.x];
}

// =================================================================================
#define SM3 65536

extern "C" void kernel_launch(void* const* d_in, const int* in_sizes, int n_in,
                              void* d_out, int out_size)
{
    const float* in1 = (const float*)d_in[0];
    const float* in2 = (const float*)d_in[1];
    const float* Wq  = (const float*)d_in[2];
    const float* bq  = (const float*)d_in[3];
    const float* Wk  = (const float*)d_in[4];
    const float* bk  = (const float*)d_in[5];
    const float* Wv  = (const float*)d_in[6];
    const float* bv  = (const float*)d_in[7];
    const int*   idx = (const int*)d_in[8];
    float* out = (float*)d_out;

    float *qp, *kp, *vp, *qksp, *attnp, *ksp, *qsp, *upp;
    cudaGetSymbolAddress((void**)&qp,   g_q);
    cudaGetSymbolAddress((void**)&kp,   g_k);
    cudaGetSymbolAddress((void**)&vp,   g_v);
    cudaGetSymbolAddress((void**)&qksp, g_qks);
    cudaGetSymbolAddress((void**)&attnp,g_attn);
    cudaGetSymbolAddress((void**)&ksp,  g_ksamp);
    cudaGetSymbolAddress((void**)&qsp,  g_qsel);
    cudaGetSymbolAddress((void**)&upp,  g_upd);

    cudaFuncSetAttribute(gemm_mma<3>, cudaFuncAttributeMaxDynamicSharedMemorySize, SM3);

    const ull sX   = (ull)256 * 4096;
    const ull sQKV = (ull)L_ * D_;
    const float AS = 1024.f, IAS = 1.f / 1024.f;

    // 1. projections: fp16-split (q,k: 3 products ~ fp32 accuracy; v: 1 pass)
    gemm_h<true, 3><<<dim3(32, 4, B_), 256>>>(
        Wq, 0ull, 512, in1, in2, sX, 4096, 256, qp, sQKV, 4096, bq, 512, AS, IAS);
    gemm_h<true, 3><<<dim3(32, 4, B_), 256>>>(
        Wk, 0ull, 512, in1, in2, sX, 4096, 256, kp, sQKV, 4096, bk, 512, AS, IAS);
    gemm_h<true, 1><<<dim3(32, 4, B_), 256>>>(
        Wv, 0ull, 512, in1, in2, sX, 4096, 256, vp, sQKV, 4096, bv, 512, AS, IAS);

    // 2. K_sample gather
    gather_ksamp<<<dim3(U_, B_), 128>>>(idx);

    // 3. QKs = q @ ksamp^T : 3xTF32 (selection-critical)
    gemm_mma<3><<<dim3(4, 32, B_), 256, SM3>>>(
        qp, sQKV, 512, ksp, (ull)UP_ * D_, 512,
        qksp, (ull)L_ * UP_, UP_, 512);

    // 4-6. M reduce, top-450, Q_sel gather
    mreduce_kernel<<<dim3(512, B_), 256>>>();
    topk_kernel<<<B_, 1024>>>();
    gather_qsel<<<dim3(U_, B_), 128>>>();

    // 7. scores = Q_sel @ K^T : fp16 1-pass
    gemm_h<false, 1><<<dim3(32, 4, B_), 256>>>(
        qsp, (ull)UP_ * D_, 512, kp, kp, sQKV, 512, 512,
        attnp, (ull)UP_ * L_, 4096, nullptr, 512, 1.f, 1.f);

    // 8. softmax
    softmax_kernel<<<dim3(U_, B_), 256>>>();

    // 9. upd = attn @ V : fp16 1-pass, V is (K x N) -> TRANSB
    gemm_h<true, 1><<<dim3(4, 4, B_), 256>>>(
        attnp, (ull)UP_ * L_, 4096, vp, vp, sQKV, 512, 4096,
        upp, (ull)UP_ * D_, 512, nullptr, 4096, 1.f, 1.f);

    // 10. mean fill + scatter
    vmean_part<<<dim3(8, B_), 512>>>();
    fill_kernel<<<dim3(512, B_), 512>>>(out);
    scatter_kernel<<<dim3(U_, B_), 128>>>(out);
}